// round 2
// baseline (speedup 1.0000x reference)
#include <cuda_runtime.h>
#include <math.h>

#define FULLMASK 0xFFFFFFFFu

// Problem constants
#define BT    64
#define PDIM  1024
#define CDIM  1024
#define TT    8
#define BB    8
#define RANK  32
#define DST   16
#define MROWS (BT * PDIM)   // 65536
#define SCALING 4.0f

// Scratch (device globals: allocation-free)
__device__ float g_red[(size_t)MROWS * RANK];
__device__ float g_redout[(size_t)MROWS * RANK];

// ---------------------------------------------------------------------------
// Kernel A: red = x @ Wdown.T      (M=65536, N=32, K=1024)
// Block: 128 rows x 32 cols. 256 threads, thread = (ty 0..15 -> 8 rows, tx 0..15 -> 2 cols)
// ---------------------------------------------------------------------------
__global__ __launch_bounds__(256) void k_down(const float* __restrict__ x,
                                              const float* __restrict__ Wdown) {
    __shared__ float xs[32 * 132];  // [k][m], pad 132
    __shared__ float ws[32 * 33];   // [k][n], pad 33

    const int tid = threadIdx.x;
    const int m0  = blockIdx.x * 128;
    const int ty  = tid >> 4;   // 0..15
    const int tx  = tid & 15;   // 0..15

    float acc[8][2];
#pragma unroll
    for (int i = 0; i < 8; i++) { acc[i][0] = 0.f; acc[i][1] = 0.f; }

    for (int kt = 0; kt < CDIM; kt += 32) {
        // load Wdown tile (32n x 32k), transpose to ws[k][n]
        {
            int n  = tid >> 3;      // 0..31
            int k4 = tid & 7;       // 0..7
            float4 v = *(const float4*)(Wdown + n * CDIM + kt + k4 * 4);
            ws[(k4 * 4 + 0) * 33 + n] = v.x;
            ws[(k4 * 4 + 1) * 33 + n] = v.y;
            ws[(k4 * 4 + 2) * 33 + n] = v.z;
            ws[(k4 * 4 + 3) * 33 + n] = v.w;
        }
        // load x tile (128m x 32k), transpose to xs[k][m]
#pragma unroll
        for (int p = 0; p < 4; p++) {
            int i   = tid + p * 256;      // f4 index 0..1023
            int row = i >> 3;
            int k4  = i & 7;
            float4 v = *(const float4*)(x + (size_t)(m0 + row) * CDIM + kt + k4 * 4);
            xs[(k4 * 4 + 0) * 132 + row] = v.x;
            xs[(k4 * 4 + 1) * 132 + row] = v.y;
            xs[(k4 * 4 + 2) * 132 + row] = v.z;
            xs[(k4 * 4 + 3) * 132 + row] = v.w;
        }
        __syncthreads();

#pragma unroll
        for (int k = 0; k < 32; k++) {
            float a[8];
            *(float4*)(a)     = *(const float4*)(xs + k * 132 + ty * 8);
            *(float4*)(a + 4) = *(const float4*)(xs + k * 132 + ty * 8 + 4);
            float b0 = ws[k * 33 + tx * 2];
            float b1 = ws[k * 33 + tx * 2 + 1];
#pragma unroll
            for (int i = 0; i < 8; i++) {
                acc[i][0] = fmaf(a[i], b0, acc[i][0]);
                acc[i][1] = fmaf(a[i], b1, acc[i][1]);
            }
        }
        __syncthreads();
    }

#pragma unroll
    for (int i = 0; i < 8; i++) {
        size_t base = (size_t)(m0 + ty * 8 + i) * RANK + tx * 2;
        g_red[base]     = acc[i][0];
        g_red[base + 1] = acc[i][1];
    }
}

// ---------------------------------------------------------------------------
// Kernel B: SSM scan. One warp per sequence (n = b*P + p), lane = rank index r.
// ---------------------------------------------------------------------------
__device__ __forceinline__ float softplusf(float v) {
    if (v > 15.0f) return v;
    return log1pf(__expf(v));
}

__global__ __launch_bounds__(256) void k_ssm(const float* __restrict__ A_log,
                                             const float* __restrict__ Dp,
                                             const float* __restrict__ Wxp,
                                             const float* __restrict__ bxp,
                                             const float* __restrict__ Wout,
                                             const float* __restrict__ bout) {
    __shared__ float sWxp[64 * 33];   // row j, pad 33
    __shared__ float sWout[32 * 33];
    __shared__ float sbxp[64];
    __shared__ float sbout[32];
    __shared__ float sDp[32];
    __shared__ float sAlog[32 * 16];

    const int tid = threadIdx.x;
    for (int i = tid; i < 64 * 32; i += blockDim.x)
        sWxp[(i >> 5) * 33 + (i & 31)] = Wxp[i];
    for (int i = tid; i < 32 * 32; i += blockDim.x)
        sWout[(i >> 5) * 33 + (i & 31)] = Wout[i];
    if (tid < 64) sbxp[tid] = bxp[tid];
    if (tid < 32) { sbout[tid] = bout[tid]; sDp[tid] = Dp[tid]; }
    for (int i = tid; i < 32 * 16; i += blockDim.x) sAlog[i] = A_log[i];
    __syncthreads();

    const int lane = tid & 31;
    const int seq  = (blockIdx.x * blockDim.x + tid) >> 5;   // 0..8191
    const int b    = seq >> 10;          // /1024
    const int p    = seq & 1023;

    float An[DST];
#pragma unroll
    for (int s = 0; s < DST; s++) An[s] = -__expf(sAlog[lane * 16 + s]);
    const float Dpr = sDp[lane];

    float h[DST];
#pragma unroll
    for (int s = 0; s < DST; s++) h[s] = 0.f;

    for (int t = 0; t < TT; t++) {
        size_t idx = ((size_t)(b * TT + t) * PDIM + p) * RANK + lane;
        float xv = g_red[idx];

        // proj = Wxp @ x_t + bxp ; lane computes proj[lane] and proj[lane+32]
        float p0 = sbxp[lane];
        float p1 = sbxp[32 + lane];
#pragma unroll
        for (int rr = 0; rr < 32; rr++) {
            float xr = __shfl_sync(FULLMASK, xv, rr);
            p0 = fmaf(sWxp[lane * 33 + rr], xr, p0);
            p1 = fmaf(sWxp[(lane + 32) * 33 + rr], xr, p1);
        }
        float dlt = softplusf(p0);

        float y = Dpr * xv;
#pragma unroll
        for (int s = 0; s < DST; s++) {
            float Bs_ = __shfl_sync(FULLMASK, p1, s);        // Bm[s] at lane s
            float Cs_ = __shfl_sync(FULLMASK, p1, 16 + s);   // Cm[s] at lane 16+s
            float Ab  = __expf(dlt * An[s]);
            h[s] = fmaf(Ab, h[s], dlt * Bs_ * xv);
            y    = fmaf(h[s], Cs_, y);
        }

        // out_t = Wout @ y + bout
        float o = sbout[lane];
#pragma unroll
        for (int rr = 0; rr < 32; rr++) {
            float yr = __shfl_sync(FULLMASK, y, rr);
            o = fmaf(sWout[lane * 33 + rr], yr, o);
        }
        g_redout[idx] = o;
    }
}

// ---------------------------------------------------------------------------
// Kernel C: out = x @ Wb.T + bb + SCALING * (redout @ Wup.T)
// M=65536, N=1024, K=1024. 128x128x16 tiles, 8x8 microtile, 256 threads,
// double-buffered smem. Epilogue fuses the K=32 delta GEMM + bias.
// ---------------------------------------------------------------------------
__global__ __launch_bounds__(256, 2) void k_big(const float* __restrict__ x,
                                                const float* __restrict__ Wb,
                                                const float* __restrict__ bb,
                                                const float* __restrict__ Wup,
                                                float* __restrict__ out) {
    __shared__ float smem[8448];   // As: 2*16*132 = 4224 ; Bs: 4224

    const int tid = threadIdx.x;
    const int m0  = blockIdx.y * 128;
    const int n0  = blockIdx.x * 128;
    const int ty  = tid >> 4;   // 0..15 -> m micro
    const int tx  = tid & 15;   // 0..15 -> n micro

    float* As = smem;
    float* Bs = smem + 4224;

    float acc[8][8];
#pragma unroll
    for (int i = 0; i < 8; i++)
#pragma unroll
        for (int j = 0; j < 8; j++) acc[i][j] = 0.f;

    const float* xg = x  + (size_t)m0 * CDIM;
    const float* wg = Wb + (size_t)n0 * CDIM;

    // f4-tile indices for this thread: two per matrix
    const int ia0 = tid, ia1 = tid + 256;        // of 512 float4 (128 rows x 4)
    const int ra0 = ia0 >> 2, ka0 = ia0 & 3;
    const int ra1 = ia1 >> 2, ka1 = ia1 & 3;

    float4 va0, va1, vb0, vb1;

    // preload tile 0
    va0 = *(const float4*)(xg + (size_t)ra0 * CDIM + ka0 * 4);
    va1 = *(const float4*)(xg + (size_t)ra1 * CDIM + ka1 * 4);
    vb0 = *(const float4*)(wg + (size_t)ra0 * CDIM + ka0 * 4);
    vb1 = *(const float4*)(wg + (size_t)ra1 * CDIM + ka1 * 4);
    {
        float* A0 = As;
        A0[(ka0 * 4 + 0) * 132 + ra0] = va0.x; A0[(ka0 * 4 + 1) * 132 + ra0] = va0.y;
        A0[(ka0 * 4 + 2) * 132 + ra0] = va0.z; A0[(ka0 * 4 + 3) * 132 + ra0] = va0.w;
        A0[(ka1 * 4 + 0) * 132 + ra1] = va1.x; A0[(ka1 * 4 + 1) * 132 + ra1] = va1.y;
        A0[(ka1 * 4 + 2) * 132 + ra1] = va1.z; A0[(ka1 * 4 + 3) * 132 + ra1] = va1.w;
        float* B0 = Bs;
        B0[(ka0 * 4 + 0) * 132 + ra0] = vb0.x; B0[(ka0 * 4 + 1) * 132 + ra0] = vb0.y;
        B0[(ka0 * 4 + 2) * 132 + ra0] = vb0.z; B0[(ka0 * 4 + 3) * 132 + ra0] = vb0.w;
        B0[(ka1 * 4 + 0) * 132 + ra1] = vb1.x; B0[(ka1 * 4 + 1) * 132 + ra1] = vb1.y;
        B0[(ka1 * 4 + 2) * 132 + ra1] = vb1.z; B0[(ka1 * 4 + 3) * 132 + ra1] = vb1.w;
    }
    __syncthreads();

    const int NT = CDIM / 16;   // 64
    for (int t = 0; t < NT; t++) {
        const int buf = t & 1;
        if (t + 1 < NT) {
            const int kt = (t + 1) * 16;
            va0 = *(const float4*)(xg + (size_t)ra0 * CDIM + kt + ka0 * 4);
            va1 = *(const float4*)(xg + (size_t)ra1 * CDIM + kt + ka1 * 4);
            vb0 = *(const float4*)(wg + (size_t)ra0 * CDIM + kt + ka0 * 4);
            vb1 = *(const float4*)(wg + (size_t)ra1 * CDIM + kt + ka1 * 4);
        }
        const float* Asb = As + buf * 2112;
        const float* Bsb = Bs + buf * 2112;
#pragma unroll
        for (int k = 0; k < 16; k++) {
            float a[8], b[8];
            *(float4*)(a)     = *(const float4*)(Asb + k * 132 + ty * 8);
            *(float4*)(a + 4) = *(const float4*)(Asb + k * 132 + ty * 8 + 4);
            *(float4*)(b)     = *(const float4*)(Bsb + k * 132 + tx * 8);
            *(float4*)(b + 4) = *(const float4*)(Bsb + k * 132 + tx * 8 + 4);
#pragma unroll
            for (int i = 0; i < 8; i++)
#pragma unroll
                for (int j = 0; j < 8; j++)
                    acc[i][j] = fmaf(a[i], b[j], acc[i][j]);
        }
        if (t + 1 < NT) {
            float* A1 = As + (buf ^ 1) * 2112;
            A1[(ka0 * 4 + 0) * 132 + ra0] = va0.x; A1[(ka0 * 4 + 1) * 132 + ra0] = va0.y;
            A1[(ka0 * 4 + 2) * 132 + ra0] = va0.z; A1[(ka0 * 4 + 3) * 132 + ra0] = va0.w;
            A1[(ka1 * 4 + 0) * 132 + ra1] = va1.x; A1[(ka1 * 4 + 1) * 132 + ra1] = va1.y;
            A1[(ka1 * 4 + 2) * 132 + ra1] = va1.z; A1[(ka1 * 4 + 3) * 132 + ra1] = va1.w;
            float* B1 = Bs + (buf ^ 1) * 2112;
            B1[(ka0 * 4 + 0) * 132 + ra0] = vb0.x; B1[(ka0 * 4 + 1) * 132 + ra0] = vb0.y;
            B1[(ka0 * 4 + 2) * 132 + ra0] = vb0.z; B1[(ka0 * 4 + 3) * 132 + ra0] = vb0.w;
            B1[(ka1 * 4 + 0) * 132 + ra1] = vb1.x; B1[(ka1 * 4 + 1) * 132 + ra1] = vb1.y;
            B1[(ka1 * 4 + 2) * 132 + ra1] = vb1.z; B1[(ka1 * 4 + 3) * 132 + ra1] = vb1.w;
        }
        __syncthreads();
    }

    // ---- epilogue: delta = SCALING * redout @ Wup.T, plus bias ----
    // redS = smem (32 x 132, pre-scaled by SCALING), WupS = smem + 4224 (32 x 132)
    {
        float* redS = smem;
        float* WupS = smem + 4224;
#pragma unroll
        for (int pp = 0; pp < 4; pp++) {
            int i   = tid + pp * 256;   // f4 index 0..1023 (128 rows x 8 f4)
            int row = i >> 3;
            int k4  = i & 7;
            float4 v = *(const float4*)(g_redout + (size_t)(m0 + row) * RANK + k4 * 4);
            redS[(k4 * 4 + 0) * 132 + row] = v.x * SCALING;
            redS[(k4 * 4 + 1) * 132 + row] = v.y * SCALING;
            redS[(k4 * 4 + 2) * 132 + row] = v.z * SCALING;
            redS[(k4 * 4 + 3) * 132 + row] = v.w * SCALING;
            float4 w = *(const float4*)(Wup + (size_t)(n0 + row) * RANK + k4 * 4);
            WupS[(k4 * 4 + 0) * 132 + row] = w.x;
            WupS[(k4 * 4 + 1) * 132 + row] = w.y;
            WupS[(k4 * 4 + 2) * 132 + row] = w.z;
            WupS[(k4 * 4 + 3) * 132 + row] = w.w;
        }
        __syncthreads();
#pragma unroll
        for (int r = 0; r < RANK; r++) {
            float a[8], b[8];
            *(float4*)(a)     = *(const float4*)(redS + r * 132 + ty * 8);
            *(float4*)(a + 4) = *(const float4*)(redS + r * 132 + ty * 8 + 4);
            *(float4*)(b)     = *(const float4*)(WupS + r * 132 + tx * 8);
            *(float4*)(b + 4) = *(const float4*)(WupS + r * 132 + tx * 8 + 4);
#pragma unroll
            for (int i = 0; i < 8; i++)
#pragma unroll
                for (int j = 0; j < 8; j++)
                    acc[i][j] = fmaf(a[i], b[j], acc[i][j]);
        }
    }

    float bbv[8];
#pragma unroll
    for (int j = 0; j < 8; j++) bbv[j] = __ldg(bb + n0 + tx * 8 + j);

#pragma unroll
    for (int i = 0; i < 8; i++) {
        float4 o0, o1;
        o0.x = acc[i][0] + bbv[0]; o0.y = acc[i][1] + bbv[1];
        o0.z = acc[i][2] + bbv[2]; o0.w = acc[i][3] + bbv[3];
        o1.x = acc[i][4] + bbv[4]; o1.y = acc[i][5] + bbv[5];
        o1.z = acc[i][6] + bbv[6]; o1.w = acc[i][7] + bbv[7];
        float* orow = out + (size_t)(m0 + ty * 8 + i) * CDIM + n0 + tx * 8;
        *(float4*)(orow)     = o0;
        *(float4*)(orow + 4) = o1;
    }
}

// ---------------------------------------------------------------------------
extern "C" void kernel_launch(void* const* d_in, const int* in_sizes, int n_in,
                              void* d_out, int out_size) {
    const float* x     = (const float*)d_in[0];
    const float* Wb    = (const float*)d_in[1];
    const float* bb    = (const float*)d_in[2];
    const float* Wdown = (const float*)d_in[3];
    const float* Wup   = (const float*)d_in[4];
    const float* A_log = (const float*)d_in[5];
    const float* Dp    = (const float*)d_in[6];
    const float* Wxp   = (const float*)d_in[7];
    const float* bxp   = (const float*)d_in[8];
    const float* Wout  = (const float*)d_in[9];
    const float* bout  = (const float*)d_in[10];
    float* out = (float*)d_out;

    // 1) red = x @ Wdown.T
    k_down<<<MROWS / 128, 256>>>(x, Wdown);

    // 2) SSM scan over 8192 sequences (one warp each)
    k_ssm<<<(MROWS / TT) * 32 / 256, 256>>>(A_log, Dp, Wxp, bxp, Wout, bout);

    // 3) out = x @ Wb.T + bb + SCALING * redout @ Wup.T
    dim3 grid(CDIM / 128, MROWS / 128);
    k_big<<<grid, 256>>>(x, Wb, bb, Wup, out);
}

// round 3
// speedup vs baseline: 1.0009x; 1.0009x over previous
#include <cuda_runtime.h>
#include <math.h>

#define FULLMASK 0xFFFFFFFFu

// Problem constants
#define BT    64
#define PDIM  1024
#define CDIM  1024
#define TT    8
#define BB    8
#define RANK  32
#define DST   16
#define MROWS (BT * PDIM)   // 65536
#define SCALING 4.0f

// Scratch (device globals: allocation-free)
__device__ float g_red[(size_t)MROWS * RANK];
__device__ float g_redout[(size_t)MROWS * RANK];

// ---------------------------------------------------------------------------
// Kernel A: red = x @ Wdown.T      (M=65536, N=32, K=1024)
// Block: 128 rows x 32 cols. 256 threads, thread = (ty 0..15 -> 8 rows, tx 0..15 -> 2 cols)
// ---------------------------------------------------------------------------
__global__ __launch_bounds__(256) void k_down(const float* __restrict__ x,
                                              const float* __restrict__ Wdown) {
    __shared__ float xs[32 * 132];  // [k][m], pad 132
    __shared__ float ws[32 * 33];   // [k][n], pad 33

    const int tid = threadIdx.x;
    const int m0  = blockIdx.x * 128;
    const int ty  = tid >> 4;   // 0..15
    const int tx  = tid & 15;   // 0..15

    float acc[8][2];
#pragma unroll
    for (int i = 0; i < 8; i++) { acc[i][0] = 0.f; acc[i][1] = 0.f; }

    for (int kt = 0; kt < CDIM; kt += 32) {
        // load Wdown tile (32n x 32k), transpose to ws[k][n]
        {
            int n  = tid >> 3;      // 0..31
            int k4 = tid & 7;       // 0..7
            float4 v = *(const float4*)(Wdown + n * CDIM + kt + k4 * 4);
            ws[(k4 * 4 + 0) * 33 + n] = v.x;
            ws[(k4 * 4 + 1) * 33 + n] = v.y;
            ws[(k4 * 4 + 2) * 33 + n] = v.z;
            ws[(k4 * 4 + 3) * 33 + n] = v.w;
        }
        // load x tile (128m x 32k), transpose to xs[k][m]
#pragma unroll
        for (int p = 0; p < 4; p++) {
            int i   = tid + p * 256;      // f4 index 0..1023
            int row = i >> 3;
            int k4  = i & 7;
            float4 v = *(const float4*)(x + (size_t)(m0 + row) * CDIM + kt + k4 * 4);
            xs[(k4 * 4 + 0) * 132 + row] = v.x;
            xs[(k4 * 4 + 1) * 132 + row] = v.y;
            xs[(k4 * 4 + 2) * 132 + row] = v.z;
            xs[(k4 * 4 + 3) * 132 + row] = v.w;
        }
        __syncthreads();

#pragma unroll
        for (int k = 0; k < 32; k++) {
            float a[8];
            *(float4*)(a)     = *(const float4*)(xs + k * 132 + ty * 8);
            *(float4*)(a + 4) = *(const float4*)(xs + k * 132 + ty * 8 + 4);
            float b0 = ws[k * 33 + tx * 2];
            float b1 = ws[k * 33 + tx * 2 + 1];
#pragma unroll
            for (int i = 0; i < 8; i++) {
                acc[i][0] = fmaf(a[i], b0, acc[i][0]);
                acc[i][1] = fmaf(a[i], b1, acc[i][1]);
            }
        }
        __syncthreads();
    }

#pragma unroll
    for (int i = 0; i < 8; i++) {
        size_t base = (size_t)(m0 + ty * 8 + i) * RANK + tx * 2;
        g_red[base]     = acc[i][0];
        g_red[base + 1] = acc[i][1];
    }
}

// ---------------------------------------------------------------------------
// Kernel B: SSM scan. One warp per sequence (n = b*P + p), lane = rank index r.
// ---------------------------------------------------------------------------
__device__ __forceinline__ float softplusf(float v) {
    if (v > 15.0f) return v;
    return log1pf(__expf(v));
}

__global__ __launch_bounds__(256) void k_ssm(const float* __restrict__ A_log,
                                             const float* __restrict__ Dp,
                                             const float* __restrict__ Wxp,
                                             const float* __restrict__ bxp,
                                             const float* __restrict__ Wout,
                                             const float* __restrict__ bout) {
    __shared__ float sWxp[64 * 33];   // row j, pad 33
    __shared__ float sWout[32 * 33];
    __shared__ float sbxp[64];
    __shared__ float sbout[32];
    __shared__ float sDp[32];
    __shared__ float sAlog[32 * 16];

    const int tid = threadIdx.x;
    for (int i = tid; i < 64 * 32; i += blockDim.x)
        sWxp[(i >> 5) * 33 + (i & 31)] = Wxp[i];
    for (int i = tid; i < 32 * 32; i += blockDim.x)
        sWout[(i >> 5) * 33 + (i & 31)] = Wout[i];
    if (tid < 64) sbxp[tid] = bxp[tid];
    if (tid < 32) { sbout[tid] = bout[tid]; sDp[tid] = Dp[tid]; }
    for (int i = tid; i < 32 * 16; i += blockDim.x) sAlog[i] = A_log[i];
    __syncthreads();

    const int lane = tid & 31;
    const int seq  = (blockIdx.x * blockDim.x + tid) >> 5;   // 0..8191
    const int b    = seq >> 10;          // /1024
    const int p    = seq & 1023;

    float An[DST];
#pragma unroll
    for (int s = 0; s < DST; s++) An[s] = -__expf(sAlog[lane * 16 + s]);
    const float Dpr = sDp[lane];

    float h[DST];
#pragma unroll
    for (int s = 0; s < DST; s++) h[s] = 0.f;

    for (int t = 0; t < TT; t++) {
        size_t idx = ((size_t)(b * TT + t) * PDIM + p) * RANK + lane;
        float xv = g_red[idx];

        // proj = Wxp @ x_t + bxp ; lane computes proj[lane] and proj[lane+32]
        float p0 = sbxp[lane];
        float p1 = sbxp[32 + lane];
#pragma unroll
        for (int rr = 0; rr < 32; rr++) {
            float xr = __shfl_sync(FULLMASK, xv, rr);
            p0 = fmaf(sWxp[lane * 33 + rr], xr, p0);
            p1 = fmaf(sWxp[(lane + 32) * 33 + rr], xr, p1);
        }
        float dlt = softplusf(p0);

        float y = Dpr * xv;
#pragma unroll
        for (int s = 0; s < DST; s++) {
            float Bs_ = __shfl_sync(FULLMASK, p1, s);        // Bm[s] at lane s
            float Cs_ = __shfl_sync(FULLMASK, p1, 16 + s);   // Cm[s] at lane 16+s
            float Ab  = __expf(dlt * An[s]);
            h[s] = fmaf(Ab, h[s], dlt * Bs_ * xv);
            y    = fmaf(h[s], Cs_, y);
        }

        // out_t = Wout @ y + bout
        float o = sbout[lane];
#pragma unroll
        for (int rr = 0; rr < 32; rr++) {
            float yr = __shfl_sync(FULLMASK, y, rr);
            o = fmaf(sWout[lane * 33 + rr], yr, o);
        }
        g_redout[idx] = o;
    }
}

// ---------------------------------------------------------------------------
// Kernel C: out = x @ Wb.T + bb + SCALING * (redout @ Wup.T)
// M=65536, N=1024, K=1024. 128x128x16 tiles, 8x8 microtile, 256 threads,
// double-buffered smem. Epilogue fuses the K=32 delta GEMM + bias.
// ---------------------------------------------------------------------------
__global__ __launch_bounds__(256, 2) void k_big(const float* __restrict__ x,
                                                const float* __restrict__ Wb,
                                                const float* __restrict__ bb,
                                                const float* __restrict__ Wup,
                                                float* __restrict__ out) {
    __shared__ float smem[8448];   // As: 2*16*132 = 4224 ; Bs: 4224

    const int tid = threadIdx.x;
    const int m0  = blockIdx.y * 128;
    const int n0  = blockIdx.x * 128;
    const int ty  = tid >> 4;   // 0..15 -> m micro
    const int tx  = tid & 15;   // 0..15 -> n micro

    float* As = smem;
    float* Bs = smem + 4224;

    float acc[8][8];
#pragma unroll
    for (int i = 0; i < 8; i++)
#pragma unroll
        for (int j = 0; j < 8; j++) acc[i][j] = 0.f;

    const float* xg = x  + (size_t)m0 * CDIM;
    const float* wg = Wb + (size_t)n0 * CDIM;

    // f4-tile indices for this thread: two per matrix
    const int ia0 = tid, ia1 = tid + 256;        // of 512 float4 (128 rows x 4)
    const int ra0 = ia0 >> 2, ka0 = ia0 & 3;
    const int ra1 = ia1 >> 2, ka1 = ia1 & 3;

    float4 va0, va1, vb0, vb1;

    // preload tile 0
    va0 = *(const float4*)(xg + (size_t)ra0 * CDIM + ka0 * 4);
    va1 = *(const float4*)(xg + (size_t)ra1 * CDIM + ka1 * 4);
    vb0 = *(const float4*)(wg + (size_t)ra0 * CDIM + ka0 * 4);
    vb1 = *(const float4*)(wg + (size_t)ra1 * CDIM + ka1 * 4);
    {
        float* A0 = As;
        A0[(ka0 * 4 + 0) * 132 + ra0] = va0.x; A0[(ka0 * 4 + 1) * 132 + ra0] = va0.y;
        A0[(ka0 * 4 + 2) * 132 + ra0] = va0.z; A0[(ka0 * 4 + 3) * 132 + ra0] = va0.w;
        A0[(ka1 * 4 + 0) * 132 + ra1] = va1.x; A0[(ka1 * 4 + 1) * 132 + ra1] = va1.y;
        A0[(ka1 * 4 + 2) * 132 + ra1] = va1.z; A0[(ka1 * 4 + 3) * 132 + ra1] = va1.w;
        float* B0 = Bs;
        B0[(ka0 * 4 + 0) * 132 + ra0] = vb0.x; B0[(ka0 * 4 + 1) * 132 + ra0] = vb0.y;
        B0[(ka0 * 4 + 2) * 132 + ra0] = vb0.z; B0[(ka0 * 4 + 3) * 132 + ra0] = vb0.w;
        B0[(ka1 * 4 + 0) * 132 + ra1] = vb1.x; B0[(ka1 * 4 + 1) * 132 + ra1] = vb1.y;
        B0[(ka1 * 4 + 2) * 132 + ra1] = vb1.z; B0[(ka1 * 4 + 3) * 132 + ra1] = vb1.w;
    }
    __syncthreads();

    const int NT = CDIM / 16;   // 64
    for (int t = 0; t < NT; t++) {
        const int buf = t & 1;
        if (t + 1 < NT) {
            const int kt = (t + 1) * 16;
            va0 = *(const float4*)(xg + (size_t)ra0 * CDIM + kt + ka0 * 4);
            va1 = *(const float4*)(xg + (size_t)ra1 * CDIM + kt + ka1 * 4);
            vb0 = *(const float4*)(wg + (size_t)ra0 * CDIM + kt + ka0 * 4);
            vb1 = *(const float4*)(wg + (size_t)ra1 * CDIM + kt + ka1 * 4);
        }
        const float* Asb = As + buf * 2112;
        const float* Bsb = Bs + buf * 2112;
#pragma unroll
        for (int k = 0; k < 16; k++) {
            float a[8], b[8];
            *(float4*)(a)     = *(const float4*)(Asb + k * 132 + ty * 8);
            *(float4*)(a + 4) = *(const float4*)(Asb + k * 132 + ty * 8 + 4);
            *(float4*)(b)     = *(const float4*)(Bsb + k * 132 + tx * 8);
            *(float4*)(b + 4) = *(const float4*)(Bsb + k * 132 + tx * 8 + 4);
#pragma unroll
            for (int i = 0; i < 8; i++)
#pragma unroll
                for (int j = 0; j < 8; j++)
                    acc[i][j] = fmaf(a[i], b[j], acc[i][j]);
        }
        if (t + 1 < NT) {
            float* A1 = As + (buf ^ 1) * 2112;
            A1[(ka0 * 4 + 0) * 132 + ra0] = va0.x; A1[(ka0 * 4 + 1) * 132 + ra0] = va0.y;
            A1[(ka0 * 4 + 2) * 132 + ra0] = va0.z; A1[(ka0 * 4 + 3) * 132 + ra0] = va0.w;
            A1[(ka1 * 4 + 0) * 132 + ra1] = va1.x; A1[(ka1 * 4 + 1) * 132 + ra1] = va1.y;
            A1[(ka1 * 4 + 2) * 132 + ra1] = va1.z; A1[(ka1 * 4 + 3) * 132 + ra1] = va1.w;
            float* B1 = Bs + (buf ^ 1) * 2112;
            B1[(ka0 * 4 + 0) * 132 + ra0] = vb0.x; B1[(ka0 * 4 + 1) * 132 + ra0] = vb0.y;
            B1[(ka0 * 4 + 2) * 132 + ra0] = vb0.z; B1[(ka0 * 4 + 3) * 132 + ra0] = vb0.w;
            B1[(ka1 * 4 + 0) * 132 + ra1] = vb1.x; B1[(ka1 * 4 + 1) * 132 + ra1] = vb1.y;
            B1[(ka1 * 4 + 2) * 132 + ra1] = vb1.z; B1[(ka1 * 4 + 3) * 132 + ra1] = vb1.w;
        }
        __syncthreads();
    }

    // ---- epilogue: delta = SCALING * redout @ Wup.T, plus bias ----
    // redS = smem (32 x 132, pre-scaled by SCALING), WupS = smem + 4224 (32 x 132)
    {
        float* redS = smem;
        float* WupS = smem + 4224;
#pragma unroll
        for (int pp = 0; pp < 4; pp++) {
            int i   = tid + pp * 256;   // f4 index 0..1023 (128 rows x 8 f4)
            int row = i >> 3;
            int k4  = i & 7;
            float4 v = *(const float4*)(g_redout + (size_t)(m0 + row) * RANK + k4 * 4);
            redS[(k4 * 4 + 0) * 132 + row] = v.x * SCALING;
            redS[(k4 * 4 + 1) * 132 + row] = v.y * SCALING;
            redS[(k4 * 4 + 2) * 132 + row] = v.z * SCALING;
            redS[(k4 * 4 + 3) * 132 + row] = v.w * SCALING;
            float4 w = *(const float4*)(Wup + (size_t)(n0 + row) * RANK + k4 * 4);
            WupS[(k4 * 4 + 0) * 132 + row] = w.x;
            WupS[(k4 * 4 + 1) * 132 + row] = w.y;
            WupS[(k4 * 4 + 2) * 132 + row] = w.z;
            WupS[(k4 * 4 + 3) * 132 + row] = w.w;
        }
        __syncthreads();
#pragma unroll
        for (int r = 0; r < RANK; r++) {
            float a[8], b[8];
            *(float4*)(a)     = *(const float4*)(redS + r * 132 + ty * 8);
            *(float4*)(a + 4) = *(const float4*)(redS + r * 132 + ty * 8 + 4);
            *(float4*)(b)     = *(const float4*)(WupS + r * 132 + tx * 8);
            *(float4*)(b + 4) = *(const float4*)(WupS + r * 132 + tx * 8 + 4);
#pragma unroll
            for (int i = 0; i < 8; i++)
#pragma unroll
                for (int j = 0; j < 8; j++)
                    acc[i][j] = fmaf(a[i], b[j], acc[i][j]);
        }
    }

    float bbv[8];
#pragma unroll
    for (int j = 0; j < 8; j++) bbv[j] = __ldg(bb + n0 + tx * 8 + j);

#pragma unroll
    for (int i = 0; i < 8; i++) {
        float4 o0, o1;
        o0.x = acc[i][0] + bbv[0]; o0.y = acc[i][1] + bbv[1];
        o0.z = acc[i][2] + bbv[2]; o0.w = acc[i][3] + bbv[3];
        o1.x = acc[i][4] + bbv[4]; o1.y = acc[i][5] + bbv[5];
        o1.z = acc[i][6] + bbv[6]; o1.w = acc[i][7] + bbv[7];
        float* orow = out + (size_t)(m0 + ty * 8 + i) * CDIM + n0 + tx * 8;
        *(float4*)(orow)     = o0;
        *(float4*)(orow + 4) = o1;
    }
}

// ---------------------------------------------------------------------------
extern "C" void kernel_launch(void* const* d_in, const int* in_sizes, int n_in,
                              void* d_out, int out_size) {
    const float* x     = (const float*)d_in[0];
    const float* Wb    = (const float*)d_in[1];
    const float* bb    = (const float*)d_in[2];
    const float* Wdown = (const float*)d_in[3];
    const float* Wup   = (const float*)d_in[4];
    const float* A_log = (const float*)d_in[5];
    const float* Dp    = (const float*)d_in[6];
    const float* Wxp   = (const float*)d_in[7];
    const float* bxp   = (const float*)d_in[8];
    const float* Wout  = (const float*)d_in[9];
    const float* bout  = (const float*)d_in[10];
    float* out = (float*)d_out;

    // 1) red = x @ Wdown.T
    k_down<<<MROWS / 128, 256>>>(x, Wdown);

    // 2) SSM scan over 8192 sequences (one warp each)
    k_ssm<<<(MROWS / TT) * 32 / 256, 256>>>(A_log, Dp, Wxp, bxp, Wout, bout);

    // 3) out = x @ Wb.T + bb + SCALING * redout @ Wup.T
    dim3 grid(CDIM / 128, MROWS / 128);
    k_big<<<grid, 256>>>(x, Wb, bb, Wup, out);
}

// round 5
// speedup vs baseline: 7.0919x; 7.0856x over previous
#include <cuda_runtime.h>
#include <cuda.h>
#include <cuda_fp16.h>
#include <math.h>

#define FULLMASK 0xFFFFFFFFu
#define BT    64
#define PDIM  1024
#define CDIM  1024
#define TT    8
#define RANK  32
#define DST   16
#define MROWS (BT * PDIM)
#define KPAD  1088
#define SCALING 4.0f

#if defined(__CUDA_ARCH_FEAT_SM103_ALL) || defined(__CUDA_ARCH_FEAT_SM100_ALL) || defined(__CUDA_ARCH_FEAT_SM101_ALL)
#define HAS_TC 1
#endif

__device__ __align__(128) __half g_xh[(size_t)MROWS * KPAD];
__device__ __align__(128) __half g_wh[(size_t)CDIM * KPAD];
__device__ float g_red[(size_t)MROWS * RANK];

// ---------------- PTX helpers ----------------
__device__ __forceinline__ uint32_t smem_u32(const void* p) {
    uint32_t a;
    asm("{ .reg .u64 t; cvta.to.shared.u64 t, %1; cvt.u32.u64 %0, t; }" : "=r"(a) : "l"(p));
    return a;
}
#define MBAR_INIT(a, c) asm volatile("mbarrier.init.shared.b64 [%0], %1;" :: "r"(a), "r"(c) : "memory")
#define MBAR_EXPECT_TX(a, b) asm volatile("mbarrier.arrive.expect_tx.shared.b64 _, [%0], %1;" :: "r"(a), "r"(b) : "memory")
#define MBAR_WAIT(a, p) do { \
    asm volatile("{\n\t.reg .pred P1;\n\tWL_%=:\n\t" \
        "mbarrier.try_wait.parity.acquire.cta.shared::cta.b64 P1, [%0], %1, 0x989680;\n\t" \
        "@P1 bra.uni WD_%=;\n\tbra.uni WL_%=;\n\tWD_%=:\n\t}" :: "r"(a), "r"(p) : "memory"); \
} while (0)
#define TMA_LOAD_2D(dst, tm, cx, cy, mb) \
    asm volatile("cp.async.bulk.tensor.2d.shared::cta.global.tile.mbarrier::complete_tx::bytes " \
        "[%0], [%1, {%2, %3}], [%4];" :: "r"(dst), "l"(tm), "r"(cx), "r"(cy), "r"(mb) : "memory")

#ifdef HAS_TC
#define TC_ALLOC(s, n) asm volatile("tcgen05.alloc.cta_group::1.sync.aligned.shared::cta.b32 [%0], %1;" :: "r"(s), "r"(n) : "memory")
#define TC_RELINQ()    asm volatile("tcgen05.relinquish_alloc_permit.cta_group::1.sync.aligned;")
#define TC_DEALLOC(t, n) asm volatile("tcgen05.dealloc.cta_group::1.sync.aligned.b32 %0, %1;" :: "r"(t), "r"(n))
#define TC_COMMIT(mb)  asm volatile("tcgen05.commit.cta_group::1.mbarrier::arrive::one.shared::cluster.b64 [%0];" :: "r"(mb) : "memory")
#define TC_FENCE_AFTER() asm volatile("tcgen05.fence::after_thread_sync;" ::: "memory")
#define TC_WAIT_LD()   asm volatile("tcgen05.wait::ld.sync.aligned;" ::: "memory")

__device__ __forceinline__ void mma_f16_ss(uint32_t d, uint64_t ad, uint64_t bd,
                                           uint32_t idesc, uint32_t accf) {
    asm volatile("{\n\t.reg .pred p;\n\tsetp.ne.u32 p, %4, 0;\n\t"
        "tcgen05.mma.cta_group::1.kind::f16 [%0], %1, %2, %3, {%5,%5,%5,%5}, p;\n\t}"
        :: "r"(d), "l"(ad), "l"(bd), "r"(idesc), "r"(accf), "r"(0u) : "memory");
}
#define TC_LD_X32(r, t) \
    asm volatile("tcgen05.ld.sync.aligned.32x32b.x32.b32 " \
        "{%0,%1,%2,%3,%4,%5,%6,%7,%8,%9,%10,%11,%12,%13,%14,%15," \
        "%16,%17,%18,%19,%20,%21,%22,%23,%24,%25,%26,%27,%28,%29,%30,%31}, [%32];" \
        : "=r"((r)[0]),"=r"((r)[1]),"=r"((r)[2]),"=r"((r)[3]),"=r"((r)[4]),"=r"((r)[5]),"=r"((r)[6]),"=r"((r)[7]), \
          "=r"((r)[8]),"=r"((r)[9]),"=r"((r)[10]),"=r"((r)[11]),"=r"((r)[12]),"=r"((r)[13]),"=r"((r)[14]),"=r"((r)[15]), \
          "=r"((r)[16]),"=r"((r)[17]),"=r"((r)[18]),"=r"((r)[19]),"=r"((r)[20]),"=r"((r)[21]),"=r"((r)[22]),"=r"((r)[23]), \
          "=r"((r)[24]),"=r"((r)[25]),"=r"((r)[26]),"=r"((r)[27]),"=r"((r)[28]),"=r"((r)[29]),"=r"((r)[30]),"=r"((r)[31]) \
        : "r"(t))
#endif

#define DESC_BASE ((2ull << 61) | (1ull << 46) | (64ull << 32) | (1ull << 16))
#define MAKE_DESC(a) (DESC_BASE | ((uint64_t)((a) >> 4) & 0x3FFF))
#define IDESC 0x8400010u

// ---------------- Kernel A: red = x @ Wdown.T, and x -> fp16 ----------------
__global__ __launch_bounds__(256) void k_down(const float* __restrict__ x,
                                              const float* __restrict__ Wdown) {
    __shared__ float xs[32 * 132];
    __shared__ float ws[32 * 33];
    const int tid = threadIdx.x;
    const int m0  = blockIdx.x * 128;
    const int ty  = tid >> 4, tx = tid & 15;

    float acc[8][2];
#pragma unroll
    for (int i = 0; i < 8; i++) { acc[i][0] = 0.f; acc[i][1] = 0.f; }

    for (int kt = 0; kt < CDIM; kt += 32) {
        {
            int n = tid >> 3, k4 = tid & 7;
            float4 v = *(const float4*)(Wdown + n * CDIM + kt + k4 * 4);
            ws[(k4*4+0)*33+n] = v.x; ws[(k4*4+1)*33+n] = v.y;
            ws[(k4*4+2)*33+n] = v.z; ws[(k4*4+3)*33+n] = v.w;
        }
#pragma unroll
        for (int p = 0; p < 4; p++) {
            int i = tid + p * 256, row = i >> 3, k4 = i & 7;
            float4 v = *(const float4*)(x + (size_t)(m0+row) * CDIM + kt + k4 * 4);
            xs[(k4*4+0)*132+row] = v.x; xs[(k4*4+1)*132+row] = v.y;
            xs[(k4*4+2)*132+row] = v.z; xs[(k4*4+3)*132+row] = v.w;
            __half2 h0 = __floats2half2_rn(v.x, v.y);
            __half2 h1 = __floats2half2_rn(v.z, v.w);
            uint2 u; u.x = *(uint32_t*)&h0; u.y = *(uint32_t*)&h1;
            *(uint2*)(g_xh + (size_t)(m0+row) * KPAD + kt + k4 * 4) = u;
        }
        __syncthreads();
#pragma unroll
        for (int k = 0; k < 32; k++) {
            float a[8];
            *(float4*)(a)   = *(const float4*)(xs + k*132 + ty*8);
            *(float4*)(a+4) = *(const float4*)(xs + k*132 + ty*8 + 4);
            float b0 = ws[k*33 + tx*2], b1 = ws[k*33 + tx*2 + 1];
#pragma unroll
            for (int i = 0; i < 8; i++) {
                acc[i][0] = fmaf(a[i], b0, acc[i][0]);
                acc[i][1] = fmaf(a[i], b1, acc[i][1]);
            }
        }
        __syncthreads();
    }
#pragma unroll
    for (int i = 0; i < 8; i++) {
        size_t base = (size_t)(m0 + ty*8 + i) * RANK + tx*2;
        g_red[base] = acc[i][0]; g_red[base+1] = acc[i][1];
    }
}

// ---------------- Kernel B: SSM scan -> g_xh cols [1024:1088) ----------------
__device__ __forceinline__ float softplusf(float v) {
    return (v > 15.0f) ? v : log1pf(__expf(v));
}

__global__ __launch_bounds__(256) void k_ssm(const float* __restrict__ A_log,
                                             const float* __restrict__ Dp,
                                             const float* __restrict__ Wxp,
                                             const float* __restrict__ bxp,
                                             const float* __restrict__ Wout,
                                             const float* __restrict__ bout) {
    __shared__ float sWxp[64 * 33], sWout[32 * 33];
    __shared__ float sbxp[64], sbout[32], sDp[32], sAlog[32 * 16];
    const int tid = threadIdx.x;
    for (int i = tid; i < 64*32; i += blockDim.x) sWxp[(i>>5)*33 + (i&31)] = Wxp[i];
    for (int i = tid; i < 32*32; i += blockDim.x) sWout[(i>>5)*33 + (i&31)] = Wout[i];
    if (tid < 64) sbxp[tid] = bxp[tid];
    if (tid < 32) { sbout[tid] = bout[tid]; sDp[tid] = Dp[tid]; }
    for (int i = tid; i < 32*16; i += blockDim.x) sAlog[i] = A_log[i];
    __syncthreads();

    const int lane = tid & 31;
    const int seq  = (blockIdx.x * blockDim.x + tid) >> 5;
    const int b = seq >> 10, p = seq & 1023;

    float An[DST];
#pragma unroll
    for (int s = 0; s < DST; s++) An[s] = -__expf(sAlog[lane*16 + s]);
    const float Dpr = sDp[lane];
    float h[DST];
#pragma unroll
    for (int s = 0; s < DST; s++) h[s] = 0.f;

    for (int t = 0; t < TT; t++) {
        size_t m = (size_t)(b * TT + t) * PDIM + p;
        float xv = g_red[m * RANK + lane];
        float p0 = sbxp[lane], p1 = sbxp[32 + lane];
#pragma unroll
        for (int rr = 0; rr < 32; rr++) {
            float xr = __shfl_sync(FULLMASK, xv, rr);
            p0 = fmaf(sWxp[lane*33 + rr], xr, p0);
            p1 = fmaf(sWxp[(lane+32)*33 + rr], xr, p1);
        }
        float dlt = softplusf(p0);
        float y = Dpr * xv;
#pragma unroll
        for (int s = 0; s < DST; s++) {
            float Bs_ = __shfl_sync(FULLMASK, p1, s);
            float Cs_ = __shfl_sync(FULLMASK, p1, 16 + s);
            float Ab  = __expf(dlt * An[s]);
            h[s] = fmaf(Ab, h[s], dlt * Bs_ * xv);
            y    = fmaf(h[s], Cs_, y);
        }
        float o = sbout[lane];
#pragma unroll
        for (int rr = 0; rr < 32; rr++) {
            float yr = __shfl_sync(FULLMASK, y, rr);
            o = fmaf(sWout[lane*33 + rr], yr, o);
        }
        g_xh[m * KPAD + 1024 + lane] = __float2half_rn(o);
        g_xh[m * KPAD + 1056 + lane] = __float2half_rn(0.f);
    }
}

// ---------------- Kernel W: B matrix fp16 = [Wb | 4*Wup | 0] ----------------
__global__ __launch_bounds__(256) void k_wb(const float* __restrict__ Wb,
                                            const float* __restrict__ Wup) {
    int idx = blockIdx.x * blockDim.x + threadIdx.x;
    if (idx >= CDIM * KPAD) return;
    int n = idx / KPAD, c = idx % KPAD;
    float v;
    if (c < 1024)      v = Wb[(size_t)n * 1024 + c];
    else if (c < 1056) v = SCALING * Wup[(size_t)n * RANK + (c - 1024)];
    else               v = 0.f;
    g_wh[idx] = __float2half_rn(v);
}

// ---------------- Kernel C: tcgen05 GEMM, D = A @ B^T + bb ----------------
#define KCH       64
#define NCHUNK    17
#define A_BYTES   (128 * 128)
#define B_BYTES   (256 * 128)
#define STG_BYTES (A_BYTES + B_BYTES)
#define SMEM_DYN  (1024 + 2 * STG_BYTES)

__global__ __launch_bounds__(256, 2) void k_big(const __grid_constant__ CUtensorMap tmA,
                                                const __grid_constant__ CUtensorMap tmB,
                                                const float* __restrict__ bb,
                                                float* __restrict__ out) {
#ifdef HAS_TC
    extern __shared__ __align__(1024) char smem[];
    const uint32_t sbase = smem_u32(smem);
    const uint32_t tslot = sbase;
    const uint32_t fullb = sbase + 16;
    const uint32_t emptb = sbase + 32;
    const uint32_t doneb = sbase + 48;

    const int tid = threadIdx.x;
    const int wid = tid >> 5, lane = tid & 31;
    const int m0 = blockIdx.y * 128;
    const int n0 = blockIdx.x * 256;

    if (tid == 0) {
        MBAR_INIT(fullb, 1); MBAR_INIT(fullb + 8, 1);
        MBAR_INIT(emptb, 1); MBAR_INIT(emptb + 8, 1);
        MBAR_INIT(doneb, 1);
    }
    if (wid == 0) { TC_ALLOC(tslot, 256); TC_RELINQ(); }
    __syncthreads();
    uint32_t tmem;
    asm volatile("ld.shared.b32 %0, [%1];" : "=r"(tmem) : "r"(tslot));

    if (tid == 0) {                 // producer
        int eph[2] = {1, 1};
        for (int c = 0; c < NCHUNK; c++) {
            int s = c & 1;
            MBAR_WAIT(emptb + s * 8, eph[s]); eph[s] ^= 1;
            uint32_t aA = sbase + 1024 + s * STG_BYTES;
            MBAR_EXPECT_TX(fullb + s * 8, STG_BYTES);
            TMA_LOAD_2D(aA, &tmA, c * KCH, m0, fullb + s * 8);
            TMA_LOAD_2D(aA + A_BYTES, &tmB, c * KCH, n0, fullb + s * 8);
        }
    } else if (tid == 32) {         // MMA issuer
        int fph[2] = {0, 0};
        for (int c = 0; c < NCHUNK; c++) {
            int s = c & 1;
            MBAR_WAIT(fullb + s * 8, fph[s]); fph[s] ^= 1;
            uint32_t aA = sbase + 1024 + s * STG_BYTES;
            uint64_t ad = MAKE_DESC(aA), bd = MAKE_DESC(aA + A_BYTES);
#pragma unroll
            for (int k = 0; k < 4; k++)
                mma_f16_ss(tmem, ad + 2 * k, bd + 2 * k, IDESC, (c | k) != 0);
            TC_COMMIT(emptb + s * 8);
        }
        TC_COMMIT(doneb);
    }

    MBAR_WAIT(doneb, 0);
    TC_FENCE_AFTER();

    const int row = m0 + (wid & 3) * 32 + lane;
    const int cb0 = (wid >> 2) * 128;
#pragma unroll
    for (int cb = 0; cb < 4; cb++) {
        uint32_t r[32];
        TC_LD_X32(r, tmem + cb0 + cb * 32);
        TC_WAIT_LD();
        const int col = n0 + cb0 + cb * 32;
        float* orow = out + (size_t)row * CDIM + col;
#pragma unroll
        for (int j = 0; j < 32; j += 4) {
            float4 v;
            v.x = __uint_as_float(r[j])     + __ldg(bb + col + j);
            v.y = __uint_as_float(r[j + 1]) + __ldg(bb + col + j + 1);
            v.z = __uint_as_float(r[j + 2]) + __ldg(bb + col + j + 2);
            v.w = __uint_as_float(r[j + 3]) + __ldg(bb + col + j + 3);
            *(float4*)(orow + j) = v;
        }
    }

    __syncthreads();
    if (wid == 0) TC_DEALLOC(tmem, 256);
#else
    // Fallback for non-'a' compile passes (must compile; not expected to run).
    const int tid = threadIdx.x;
    const int m0 = blockIdx.y * 128;
    const int n0 = blockIdx.x * 256;
    for (int e = tid; e < 128 * 256; e += 256) {
        int r = e >> 8, c = e & 255;
        const __half2* a = (const __half2*)(g_xh + (size_t)(m0 + r) * KPAD);
        const __half2* w = (const __half2*)(g_wh + (size_t)(n0 + c) * KPAD);
        float acc = 0.f;
        for (int k = 0; k < KPAD / 2; k++) {
            float2 av = __half22float2(a[k]);
            float2 wv = __half22float2(w[k]);
            acc = fmaf(av.x, wv.x, acc);
            acc = fmaf(av.y, wv.y, acc);
        }
        out[(size_t)(m0 + r) * CDIM + n0 + c] = acc + __ldg(bb + n0 + c);
    }
#endif
}

// ---------------- Host ----------------
typedef CUresult (*EncodeFn)(CUtensorMap*, CUtensorMapDataType, cuuint32_t, void*,
                             const cuuint64_t*, const cuuint64_t*, const cuuint32_t*,
                             const cuuint32_t*, CUtensorMapInterleave, CUtensorMapSwizzle,
                             CUtensorMapL2promotion, CUtensorMapFloatOOBfill);

static void make_map(EncodeFn enc, CUtensorMap* tm, void* ptr, uint64_t d0, uint64_t d1,
                     uint32_t b0, uint32_t b1) {
    cuuint64_t dims[2]    = {d0, d1};
    cuuint64_t strides[1] = {d0 * 2};
    cuuint32_t box[2]     = {b0, b1};
    cuuint32_t es[2]      = {1, 1};
    enc(tm, CU_TENSOR_MAP_DATA_TYPE_FLOAT16, 2, ptr, dims, strides, box, es,
        CU_TENSOR_MAP_INTERLEAVE_NONE, CU_TENSOR_MAP_SWIZZLE_128B,
        CU_TENSOR_MAP_L2_PROMOTION_L2_128B, CU_TENSOR_MAP_FLOAT_OOB_FILL_NONE);
}

extern "C" void kernel_launch(void* const* d_in, const int* in_sizes, int n_in,
                              void* d_out, int out_size) {
    const float* x     = (const float*)d_in[0];
    const float* Wb    = (const float*)d_in[1];
    const float* bb    = (const float*)d_in[2];
    const float* Wdown = (const float*)d_in[3];
    const float* Wup   = (const float*)d_in[4];
    const float* A_log = (const float*)d_in[5];
    const float* Dp    = (const float*)d_in[6];
    const float* Wxp   = (const float*)d_in[7];
    const float* bxp   = (const float*)d_in[8];
    const float* Wout  = (const float*)d_in[9];
    const float* bout  = (const float*)d_in[10];
    float* out = (float*)d_out;

    void* fn = nullptr;
    cudaDriverEntryPointQueryResult qr;
    cudaGetDriverEntryPointByVersion("cuTensorMapEncodeTiled", &fn, CUDART_VERSION,
                                     cudaEnableDefault, &qr);
    EncodeFn enc = (EncodeFn)fn;

    void *xh_ptr, *wh_ptr;
    cudaGetSymbolAddress(&xh_ptr, g_xh);
    cudaGetSymbolAddress(&wh_ptr, g_wh);

    CUtensorMap tmA, tmB;
    make_map(enc, &tmA, xh_ptr, KPAD, MROWS, KCH, 128);
    make_map(enc, &tmB, wh_ptr, KPAD, CDIM, KCH, 256);

    cudaFuncSetAttribute(k_big, cudaFuncAttributeMaxDynamicSharedMemorySize, SMEM_DYN);

    k_down<<<MROWS / 128, 256>>>(x, Wdown);
    k_ssm<<<(MROWS / TT) * 32 / 256, 256>>>(A_log, Dp, Wxp, bxp, Wout, bout);
    k_wb<<<(CDIM * KPAD + 255) / 256, 256>>>(Wb, Wup);

    dim3 grid(CDIM / 256, MROWS / 128);
    k_big<<<grid, 256, SMEM_DYN>>>(tmA, tmB, bb, out);
}

// round 6
// speedup vs baseline: 8.7173x; 1.2292x over previous
#include <cuda_runtime.h>
#include <cuda.h>
#include <cuda_fp16.h>
#include <math.h>

#define FULLMASK 0xFFFFFFFFu
#define BT    64
#define PDIM  1024
#define CDIM  1024
#define TT    8
#define RANK  32
#define DST   16
#define MROWS (BT * PDIM)
#define KPAD  1088
#define SCALING 4.0f

#if defined(__CUDA_ARCH_FEAT_SM103_ALL) || defined(__CUDA_ARCH_FEAT_SM100_ALL) || defined(__CUDA_ARCH_FEAT_SM101_ALL)
#define HAS_TC 1
#endif

__device__ __align__(128) __half g_xh[(size_t)MROWS * KPAD];
__device__ __align__(128) __half g_wh[(size_t)CDIM * KPAD];
__device__ __align__(128) __half g_wdh[(size_t)RANK * CDIM];
__device__ float g_red[(size_t)MROWS * RANK];

// ---------------- PTX helpers ----------------
__device__ __forceinline__ uint32_t smem_u32(const void* p) {
    uint32_t a;
    asm("{ .reg .u64 t; cvta.to.shared.u64 t, %1; cvt.u32.u64 %0, t; }" : "=r"(a) : "l"(p));
    return a;
}
#define MBAR_INIT(a, c) asm volatile("mbarrier.init.shared.b64 [%0], %1;" :: "r"(a), "r"(c) : "memory")
#define MBAR_EXPECT_TX(a, b) asm volatile("mbarrier.arrive.expect_tx.shared.b64 _, [%0], %1;" :: "r"(a), "r"(b) : "memory")
#define MBAR_WAIT(a, p) do { \
    asm volatile("{\n\t.reg .pred P1;\n\tWL_%=:\n\t" \
        "mbarrier.try_wait.parity.acquire.cta.shared::cta.b64 P1, [%0], %1, 0x989680;\n\t" \
        "@P1 bra.uni WD_%=;\n\tbra.uni WL_%=;\n\tWD_%=:\n\t}" :: "r"(a), "r"(p) : "memory"); \
} while (0)
#define TMA_LOAD_2D(dst, tm, cx, cy, mb) \
    asm volatile("cp.async.bulk.tensor.2d.shared::cta.global.tile.mbarrier::complete_tx::bytes " \
        "[%0], [%1, {%2, %3}], [%4];" :: "r"(dst), "l"(tm), "r"(cx), "r"(cy), "r"(mb) : "memory")
#define CLUSTER_ARRIVE() asm volatile("barrier.cluster.arrive.aligned;" ::: "memory")
#define CLUSTER_WAIT()   asm volatile("barrier.cluster.wait.aligned;" ::: "memory")

#ifdef HAS_TC
#define TC_ALLOC(s, n) asm volatile("tcgen05.alloc.cta_group::1.sync.aligned.shared::cta.b32 [%0], %1;" :: "r"(s), "r"(n) : "memory")
#define TC_RELINQ()    asm volatile("tcgen05.relinquish_alloc_permit.cta_group::1.sync.aligned;")
#define TC_DEALLOC(t, n) asm volatile("tcgen05.dealloc.cta_group::1.sync.aligned.b32 %0, %1;" :: "r"(t), "r"(n))
#define TC_COMMIT(mb)  asm volatile("tcgen05.commit.cta_group::1.mbarrier::arrive::one.shared::cluster.b64 [%0];" :: "r"(mb) : "memory")
#define TC_ALLOC2(s, n) asm volatile("tcgen05.alloc.cta_group::2.sync.aligned.shared::cta.b32 [%0], %1;" :: "r"(s), "r"(n) : "memory")
#define TC_RELINQ2()    asm volatile("tcgen05.relinquish_alloc_permit.cta_group::2.sync.aligned;")
#define TC_DEALLOC2(t, n) asm volatile("tcgen05.dealloc.cta_group::2.sync.aligned.b32 %0, %1;" :: "r"(t), "r"(n))
#define TC_COMMIT_MC2(mb, mask) \
    asm volatile("tcgen05.commit.cta_group::2.mbarrier::arrive::one.shared::cluster.multicast::cluster.b64 [%0], %1;" \
                 :: "r"(mb), "h"((unsigned short)(mask)) : "memory")
#define TC_FENCE_AFTER() asm volatile("tcgen05.fence::after_thread_sync;" ::: "memory")
#define TC_WAIT_LD()   asm volatile("tcgen05.wait::ld.sync.aligned;" ::: "memory")
#define TMA_LOAD_2D_CG2(dst, tm, cx, cy, mb) \
    asm volatile("{\n\t.reg .b32 lb;\n\tand.b32 lb, %4, 0xFEFFFFFF;\n\t" \
        "cp.async.bulk.tensor.2d.cta_group::2.shared::cluster.global.tile.mbarrier::complete_tx::bytes " \
        "[%0], [%1, {%2, %3}], [lb];\n\t}" :: "r"(dst), "l"(tm), "r"(cx), "r"(cy), "r"(mb) : "memory")

__device__ __forceinline__ void mma_f16_ss(uint32_t d, uint64_t ad, uint64_t bd,
                                           uint32_t idesc, uint32_t accf) {
    asm volatile("{\n\t.reg .pred p;\n\tsetp.ne.u32 p, %4, 0;\n\t"
        "tcgen05.mma.cta_group::1.kind::f16 [%0], %1, %2, %3, {%5,%5,%5,%5}, p;\n\t}"
        :: "r"(d), "l"(ad), "l"(bd), "r"(idesc), "r"(accf), "r"(0u) : "memory");
}
__device__ __forceinline__ void mma_f16_ss_cg2(uint32_t d, uint64_t ad, uint64_t bd,
                                               uint32_t idesc, uint32_t accf) {
    asm volatile("{\n\t.reg .pred p;\n\tsetp.ne.u32 p, %4, 0;\n\t"
        "tcgen05.mma.cta_group::2.kind::f16 [%0], %1, %2, %3, {%5,%5,%5,%5,%5,%5,%5,%5}, p;\n\t}"
        :: "r"(d), "l"(ad), "l"(bd), "r"(idesc), "r"(accf), "r"(0u) : "memory");
}
#define TC_LD_X32(r, t) \
    asm volatile("tcgen05.ld.sync.aligned.32x32b.x32.b32 " \
        "{%0,%1,%2,%3,%4,%5,%6,%7,%8,%9,%10,%11,%12,%13,%14,%15," \
        "%16,%17,%18,%19,%20,%21,%22,%23,%24,%25,%26,%27,%28,%29,%30,%31}, [%32];" \
        : "=r"((r)[0]),"=r"((r)[1]),"=r"((r)[2]),"=r"((r)[3]),"=r"((r)[4]),"=r"((r)[5]),"=r"((r)[6]),"=r"((r)[7]), \
          "=r"((r)[8]),"=r"((r)[9]),"=r"((r)[10]),"=r"((r)[11]),"=r"((r)[12]),"=r"((r)[13]),"=r"((r)[14]),"=r"((r)[15]), \
          "=r"((r)[16]),"=r"((r)[17]),"=r"((r)[18]),"=r"((r)[19]),"=r"((r)[20]),"=r"((r)[21]),"=r"((r)[22]),"=r"((r)[23]), \
          "=r"((r)[24]),"=r"((r)[25]),"=r"((r)[26]),"=r"((r)[27]),"=r"((r)[28]),"=r"((r)[29]),"=r"((r)[30]),"=r"((r)[31]) \
        : "r"(t))
#endif

#define DESC_BASE ((2ull << 61) | (1ull << 46) | (64ull << 32) | (1ull << 16))
#define MAKE_DESC(a) (DESC_BASE | ((uint64_t)((a) >> 4) & 0x3FFF))
#define IDESC_BIG 0x10400010u   /* cg2: F32 acc, f16, M=256, N=256 */
#define IDESC_RED 0x8080010u    /* cg1: F32 acc, f16, M=128, N=32  */

// ---------------- k_conv: x fp32 -> fp16 into g_xh[:, 0:1024) ----------------
__global__ __launch_bounds__(256) void k_conv(const float* __restrict__ x) {
    size_t i = (size_t)blockIdx.x * 256 + threadIdx.x;
    size_t base = i * 8;                  // element index in 65536x1024
    size_t row = base >> 10, col = base & 1023;
    float4 v0 = *(const float4*)(x + base);
    float4 v1 = *(const float4*)(x + base + 4);
    __half2 h0 = __floats2half2_rn(v0.x, v0.y);
    __half2 h1 = __floats2half2_rn(v0.z, v0.w);
    __half2 h2 = __floats2half2_rn(v1.x, v1.y);
    __half2 h3 = __floats2half2_rn(v1.z, v1.w);
    uint4 u;
    u.x = *(uint32_t*)&h0; u.y = *(uint32_t*)&h1;
    u.z = *(uint32_t*)&h2; u.w = *(uint32_t*)&h3;
    *(uint4*)(g_xh + row * KPAD + col) = u;
}

// ---------------- k_wd: Wdown -> fp16 ----------------
__global__ __launch_bounds__(256) void k_wd(const float* __restrict__ Wdown) {
    int idx = blockIdx.x * 256 + threadIdx.x;
    if (idx < RANK * CDIM) g_wdh[idx] = __float2half_rn(Wdown[idx]);
}

// ---------------- k_wb: B matrix fp16 = [Wb | 4*Wup | 0] ----------------
__global__ __launch_bounds__(256) void k_wb(const float* __restrict__ Wb,
                                            const float* __restrict__ Wup) {
    int idx = blockIdx.x * blockDim.x + threadIdx.x;
    if (idx >= CDIM * KPAD) return;
    int n = idx / KPAD, c = idx % KPAD;
    float v;
    if (c < 1024)      v = Wb[(size_t)n * 1024 + c];
    else if (c < 1056) v = SCALING * Wup[(size_t)n * RANK + (c - 1024)];
    else               v = 0.f;
    g_wh[idx] = __float2half_rn(v);
}

// ---------------- k_red: red = xh @ Wdown.T via tcgen05 (M=65536,N=32,K=1024) ----------------
#define R_KCH    64
#define R_NCH    16
#define R_ABYTES (128 * 128)
#define R_BBYTES (32 * 128)
#define R_STG    (R_ABYTES + R_BBYTES)     // 20480
#define R_SMEM   (1024 + 3 * R_STG)        // 62464

__global__ __launch_bounds__(128) void k_red(const __grid_constant__ CUtensorMap tmA,
                                             const __grid_constant__ CUtensorMap tmB) {
#ifdef HAS_TC
    extern __shared__ __align__(1024) char smem[];
    const uint32_t sbase = smem_u32(smem);
    const uint32_t tslot = sbase;
    const uint32_t fullb = sbase + 16;   // 3 x 8B
    const uint32_t emptb = sbase + 48;   // 3 x 8B
    const uint32_t doneb = sbase + 80;
    const int tid = threadIdx.x, wid = tid >> 5, lane = tid & 31;
    const int m0 = blockIdx.x * 128;

    if (tid == 0) {
        MBAR_INIT(fullb, 1); MBAR_INIT(fullb + 8, 1); MBAR_INIT(fullb + 16, 1);
        MBAR_INIT(emptb, 1); MBAR_INIT(emptb + 8, 1); MBAR_INIT(emptb + 16, 1);
        MBAR_INIT(doneb, 1);
    }
    if (wid == 0) { TC_ALLOC(tslot, 64); TC_RELINQ(); }
    __syncthreads();
    uint32_t tmem;
    asm volatile("ld.shared.b32 %0, [%1];" : "=r"(tmem) : "r"(tslot));

    if (tid == 0) {
        int eph[3] = {1, 1, 1};
        for (int c = 0; c < R_NCH; c++) {
            int s = c % 3;
            MBAR_WAIT(emptb + s * 8, eph[s]); eph[s] ^= 1;
            uint32_t aA = sbase + 1024 + s * R_STG;
            MBAR_EXPECT_TX(fullb + s * 8, R_STG);
            TMA_LOAD_2D(aA, &tmA, c * R_KCH, m0, fullb + s * 8);
            TMA_LOAD_2D(aA + R_ABYTES, &tmB, c * R_KCH, 0, fullb + s * 8);
        }
    } else if (tid == 33) {
        int fph[3] = {0, 0, 0};
        for (int c = 0; c < R_NCH; c++) {
            int s = c % 3;
            MBAR_WAIT(fullb + s * 8, fph[s]); fph[s] ^= 1;
            uint32_t aA = sbase + 1024 + s * R_STG;
            uint64_t ad = MAKE_DESC(aA), bd = MAKE_DESC(aA + R_ABYTES);
#pragma unroll
            for (int k = 0; k < 4; k++)
                mma_f16_ss(tmem, ad + 2 * k, bd + 2 * k, IDESC_RED, (c | k) != 0);
            TC_COMMIT(emptb + s * 8);
        }
        TC_COMMIT(doneb);
    }

    MBAR_WAIT(doneb, 0);
    TC_FENCE_AFTER();

    uint32_t r[32];
    TC_LD_X32(r, tmem);
    TC_WAIT_LD();
    float* gr = g_red + (size_t)(m0 + wid * 32 + lane) * RANK;
#pragma unroll
    for (int j = 0; j < 32; j += 4) {
        float4 v;
        v.x = __uint_as_float(r[j]);     v.y = __uint_as_float(r[j + 1]);
        v.z = __uint_as_float(r[j + 2]); v.w = __uint_as_float(r[j + 3]);
        *(float4*)(gr + j) = v;
    }
    __syncthreads();
    if (wid == 0) TC_DEALLOC(tmem, 64);
#else
    const int tid = threadIdx.x;
    const int m0 = blockIdx.x * 128;
    for (int e = tid; e < 128 * RANK; e += 128) {
        int r = e >> 5, n = e & 31;
        const __half* a = g_xh + (size_t)(m0 + r) * KPAD;
        const __half* w = g_wdh + (size_t)n * CDIM;
        float acc = 0.f;
        for (int k = 0; k < CDIM; k++)
            acc = fmaf(__half2float(a[k]), __half2float(w[k]), acc);
        g_red[(size_t)(m0 + r) * RANK + n] = acc;
    }
#endif
}

// ---------------- k_ssm: scan -> g_xh cols [1024:1088) ----------------
__device__ __forceinline__ float softplusf(float v) {
    return (v > 15.0f) ? v : log1pf(__expf(v));
}

__global__ __launch_bounds__(256) void k_ssm(const float* __restrict__ A_log,
                                             const float* __restrict__ Dp,
                                             const float* __restrict__ Wxp,
                                             const float* __restrict__ bxp,
                                             const float* __restrict__ Wout,
                                             const float* __restrict__ bout) {
    __shared__ float sWxp[64 * 33], sWout[32 * 33];
    __shared__ float sbxp[64], sbout[32], sDp[32], sAlog[32 * 16];
    const int tid = threadIdx.x;
    for (int i = tid; i < 64*32; i += blockDim.x) sWxp[(i>>5)*33 + (i&31)] = Wxp[i];
    for (int i = tid; i < 32*32; i += blockDim.x) sWout[(i>>5)*33 + (i&31)] = Wout[i];
    if (tid < 64) sbxp[tid] = bxp[tid];
    if (tid < 32) { sbout[tid] = bout[tid]; sDp[tid] = Dp[tid]; }
    for (int i = tid; i < 32*16; i += blockDim.x) sAlog[i] = A_log[i];
    __syncthreads();

    const int lane = tid & 31;
    const int seq  = (blockIdx.x * blockDim.x + tid) >> 5;
    const int b = seq >> 10, p = seq & 1023;

    float An[DST];
#pragma unroll
    for (int s = 0; s < DST; s++) An[s] = -__expf(sAlog[lane*16 + s]);
    const float Dpr = sDp[lane];
    float h[DST];
#pragma unroll
    for (int s = 0; s < DST; s++) h[s] = 0.f;

    for (int t = 0; t < TT; t++) {
        size_t m = (size_t)(b * TT + t) * PDIM + p;
        float xv = g_red[m * RANK + lane];
        float p0 = sbxp[lane], p1 = sbxp[32 + lane];
#pragma unroll
        for (int rr = 0; rr < 32; rr++) {
            float xr = __shfl_sync(FULLMASK, xv, rr);
            p0 = fmaf(sWxp[lane*33 + rr], xr, p0);
            p1 = fmaf(sWxp[(lane+32)*33 + rr], xr, p1);
        }
        float dlt = softplusf(p0);
        float y = Dpr * xv;
#pragma unroll
        for (int s = 0; s < DST; s++) {
            float Bs_ = __shfl_sync(FULLMASK, p1, s);
            float Cs_ = __shfl_sync(FULLMASK, p1, 16 + s);
            float Ab  = __expf(dlt * An[s]);
            h[s] = fmaf(Ab, h[s], dlt * Bs_ * xv);
            y    = fmaf(h[s], Cs_, y);
        }
        float o = sbout[lane];
#pragma unroll
        for (int rr = 0; rr < 32; rr++) {
            float yr = __shfl_sync(FULLMASK, y, rr);
            o = fmaf(sWout[lane*33 + rr], yr, o);
        }
        g_xh[m * KPAD + 1024 + lane] = __float2half_rn(o);
        g_xh[m * KPAD + 1056 + lane] = __float2half_rn(0.f);
    }
}

// ---------------- k_big: cg2 GEMM, D[256x256 per pair] = A @ B^T + bb ----------------
#define KCH       64
#define NCHUNK    17
#define A_BYTES   (128 * 128)
#define B_BYTES   (128 * 128)
#define STG_BYTES (A_BYTES + B_BYTES)      // 32768
#define SMEM_DYN  (1024 + 3 * STG_BYTES)   // 99328

__global__ __launch_bounds__(256, 2) __cluster_dims__(2, 1, 1)
void k_big(const __grid_constant__ CUtensorMap tmA,
           const __grid_constant__ CUtensorMap tmB,
           const float* __restrict__ bb,
           float* __restrict__ out) {
#ifdef HAS_TC
    extern __shared__ __align__(1024) char smem[];
    const uint32_t sbase = smem_u32(smem);
    const uint32_t tslot = sbase;
    const uint32_t fullb = sbase + 16;   // 3 x 8B (leader's used)
    const uint32_t emptb = sbase + 48;   // 3 x 8B (per CTA)
    const uint32_t doneb = sbase + 80;

    const int tid = threadIdx.x, wid = tid >> 5, lane = tid & 31;
    uint32_t rank;
    asm("mov.u32 %0, %%cluster_ctarank;" : "=r"(rank));
    const int mrow = blockIdx.z * 256 + (int)rank * 128;   // this CTA's A rows
    const int nrow = blockIdx.y * 256 + (int)rank * 128;   // this CTA's B rows

    if (tid == 0) {
        MBAR_INIT(fullb, 1); MBAR_INIT(fullb + 8, 1); MBAR_INIT(fullb + 16, 1);
        MBAR_INIT(emptb, 1); MBAR_INIT(emptb + 8, 1); MBAR_INIT(emptb + 16, 1);
        MBAR_INIT(doneb, 1);
    }
    if (wid == 0) { TC_ALLOC2(tslot, 256); TC_RELINQ2(); }
    __syncthreads();
    uint32_t tmem;
    asm volatile("ld.shared.b32 %0, [%1];" : "=r"(tmem) : "r"(tslot));

    // all barriers + TMEM visible cluster-wide before any cg2 TMA / commit
    CLUSTER_ARRIVE(); CLUSTER_WAIT();

    if (tid == 0) {                 // producer (both CTAs)
        int eph[3] = {1, 1, 1};
        for (int c = 0; c < NCHUNK; c++) {
            int s = c % 3;
            MBAR_WAIT(emptb + s * 8, eph[s]); eph[s] ^= 1;
            uint32_t aA = sbase + 1024 + s * STG_BYTES;
            if (rank == 0) MBAR_EXPECT_TX(fullb + s * 8, 2 * STG_BYTES);
            TMA_LOAD_2D_CG2(aA, &tmA, c * KCH, mrow, fullb + s * 8);
            TMA_LOAD_2D_CG2(aA + A_BYTES, &tmB, c * KCH, nrow, fullb + s * 8);
        }
    } else if (tid == 32 && rank == 0) {   // MMA issuer (leader only)
        int fph[3] = {0, 0, 0};
        for (int c = 0; c < NCHUNK; c++) {
            int s = c % 3;
            MBAR_WAIT(fullb + s * 8, fph[s]); fph[s] ^= 1;
            uint32_t aA = sbase + 1024 + s * STG_BYTES;
            uint64_t ad = MAKE_DESC(aA), bd = MAKE_DESC(aA + A_BYTES);
#pragma unroll
            for (int k = 0; k < 4; k++)
                mma_f16_ss_cg2(tmem, ad + 2 * k, bd + 2 * k, IDESC_BIG, (c | k) != 0);
            TC_COMMIT_MC2(emptb + s * 8, 3);
        }
        TC_COMMIT_MC2(doneb, 3);
    }

    MBAR_WAIT(doneb, 0);
    TC_FENCE_AFTER();

    // epilogue: this CTA owns its 128 M rows x 256 N cols in TMEM
    const int row = mrow + (wid & 3) * 32 + lane;
    const int cb0 = (wid >> 2) * 128;
    const int ncol0 = blockIdx.y * 256;
#pragma unroll
    for (int cb = 0; cb < 4; cb++) {
        uint32_t r[32];
        TC_LD_X32(r, tmem + cb0 + cb * 32);
        TC_WAIT_LD();
        const int col = ncol0 + cb0 + cb * 32;
        float* orow = out + (size_t)row * CDIM + col;
#pragma unroll
        for (int j = 0; j < 32; j += 4) {
            float4 v;
            v.x = __uint_as_float(r[j])     + __ldg(bb + col + j);
            v.y = __uint_as_float(r[j + 1]) + __ldg(bb + col + j + 1);
            v.z = __uint_as_float(r[j + 2]) + __ldg(bb + col + j + 2);
            v.w = __uint_as_float(r[j + 3]) + __ldg(bb + col + j + 3);
            *(float4*)(orow + j) = v;
        }
    }

    __syncthreads();
    if (wid == 0) TC_DEALLOC2(tmem, 256);
    CLUSTER_ARRIVE(); CLUSTER_WAIT();
#else
    // Fallback for non-'a' compile passes (must compile; not expected to run).
    const int tid = threadIdx.x;
    const int m0 = blockIdx.z * 256 + blockIdx.x * 128;
    const int n0 = blockIdx.y * 256;
    for (int e = tid; e < 128 * 256; e += 256) {
        int r = e >> 8, c = e & 255;
        const __half2* a = (const __half2*)(g_xh + (size_t)(m0 + r) * KPAD);
        const __half2* w = (const __half2*)(g_wh + (size_t)(n0 + c) * KPAD);
        float acc = 0.f;
        for (int k = 0; k < KPAD / 2; k++) {
            float2 av = __half22float2(a[k]);
            float2 wv = __half22float2(w[k]);
            acc = fmaf(av.x, wv.x, acc);
            acc = fmaf(av.y, wv.y, acc);
        }
        out[(size_t)(m0 + r) * CDIM + n0 + c] = acc + __ldg(bb + n0 + c);
    }
#endif
}

// ---------------- Host ----------------
typedef CUresult (*EncodeFn)(CUtensorMap*, CUtensorMapDataType, cuuint32_t, void*,
                             const cuuint64_t*, const cuuint64_t*, const cuuint32_t*,
                             const cuuint32_t*, CUtensorMapInterleave, CUtensorMapSwizzle,
                             CUtensorMapL2promotion, CUtensorMapFloatOOBfill);

static void make_map(EncodeFn enc, CUtensorMap* tm, void* ptr, uint64_t d0, uint64_t d1,
                     uint32_t b0, uint32_t b1) {
    cuuint64_t dims[2]    = {d0, d1};
    cuuint64_t strides[1] = {d0 * 2};
    cuuint32_t box[2]     = {b0, b1};
    cuuint32_t es[2]      = {1, 1};
    enc(tm, CU_TENSOR_MAP_DATA_TYPE_FLOAT16, 2, ptr, dims, strides, box, es,
        CU_TENSOR_MAP_INTERLEAVE_NONE, CU_TENSOR_MAP_SWIZZLE_128B,
        CU_TENSOR_MAP_L2_PROMOTION_L2_128B, CU_TENSOR_MAP_FLOAT_OOB_FILL_NONE);
}

extern "C" void kernel_launch(void* const* d_in, const int* in_sizes, int n_in,
                              void* d_out, int out_size) {
    const float* x     = (const float*)d_in[0];
    const float* Wb    = (const float*)d_in[1];
    const float* bb    = (const float*)d_in[2];
    const float* Wdown = (const float*)d_in[3];
    const float* Wup   = (const float*)d_in[4];
    const float* A_log = (const float*)d_in[5];
    const float* Dp    = (const float*)d_in[6];
    const float* Wxp   = (const float*)d_in[7];
    const float* bxp   = (const float*)d_in[8];
    const float* Wout  = (const float*)d_in[9];
    const float* bout  = (const float*)d_in[10];
    float* out = (float*)d_out;

    void* fn = nullptr;
    cudaDriverEntryPointQueryResult qr;
    cudaGetDriverEntryPointByVersion("cuTensorMapEncodeTiled", &fn, CUDART_VERSION,
                                     cudaEnableDefault, &qr);
    EncodeFn enc = (EncodeFn)fn;

    void *xh_ptr, *wh_ptr, *wdh_ptr;
    cudaGetSymbolAddress(&xh_ptr, g_xh);
    cudaGetSymbolAddress(&wh_ptr, g_wh);
    cudaGetSymbolAddress(&wdh_ptr, g_wdh);

    CUtensorMap tmA, tmB, tmWd;
    make_map(enc, &tmA,  xh_ptr,  KPAD, MROWS, KCH, 128);    // A tiles (k_big + k_red)
    make_map(enc, &tmB,  wh_ptr,  KPAD, CDIM,  KCH, 128);    // B tiles, 128 N-rows per CTA
    make_map(enc, &tmWd, wdh_ptr, CDIM, RANK,  R_KCH, 32);   // Wdown fp16

    cudaFuncSetAttribute(k_big, cudaFuncAttributeMaxDynamicSharedMemorySize, SMEM_DYN);
    cudaFuncSetAttribute(k_red, cudaFuncAttributeMaxDynamicSharedMemorySize, R_SMEM);

    k_conv<<<(size_t)MROWS * 1024 / 8 / 256, 256>>>(x);
    k_wd<<<(RANK * CDIM + 255) / 256, 256>>>(Wdown);
    k_wb<<<(CDIM * KPAD + 255) / 256, 256>>>(Wb, Wup);
    k_red<<<MROWS / 128, 128, R_SMEM>>>(tmA, tmWd);
    k_ssm<<<(MROWS / TT) * 32 / 256, 256>>>(A_log, Dp, Wxp, bxp, Wout, bout);

    dim3 grid(2, CDIM / 256, MROWS / 256);
    k_big<<<grid, 256, SMEM_DYN>>>(tmA, tmB, bb, out);
}